// round 5
// baseline (speedup 1.0000x reference)
#include <cuda_runtime.h>
#include <cuda_bf16.h>
#include <math.h>

// instant-NGP HashGrid + 2-layer MLP, fused. 2 lanes/point, bf16x2 MLP.
// R5: persistent grid (888 CTAs = 6/SM x 148, grid-stride over batches) to
// kill the 2.31-wave quantization tail, + cooperative warp-level point loads
// (2 coalesced LDG + shuffles instead of 3 strided LDG per thread).

#define NPTS (64 * 64 * 64)
#define NLEV 16
#define TSIZE (1u << 19)
#define TMASK (TSIZE - 1u)

#define NBATCH (NPTS * 2 / 256)   // 2048 CTA-sized batches
#define NCTA 888                  // 6 per SM x 148 SMs

__device__ __nv_bfloat162 g_w1p[64 * 16];   // [j][l] packed pairs of w1[j, 2l:2l+2]

__global__ void prep_weights_kernel(const float* __restrict__ w1) {
    for (int k = threadIdx.x; k < 64 * 16; k += 256) {
        const int j = k >> 4, l = k & 15;
        g_w1p[k] = __floats2bfloat162_rn(w1[j * 32 + 2 * l], w1[j * 32 + 2 * l + 1]);
    }
}

__device__ __forceinline__ int level_res(int l) {
    const int R[NLEV] = {16, 23, 33, 48, 70, 101, 147, 212,
                         307, 445, 645, 933, 1351, 1955, 2830, 4096};
    return R[l];
}

__global__ void __launch_bounds__(256, 6)
ngp_fused_r5_kernel(const float* __restrict__ pts,
                    const float2* __restrict__ table,   // [L*T] float2
                    const float* __restrict__ w2,       // [64]
                    float* __restrict__ out)            // [NPTS]
{
    __shared__ __nv_bfloat162 s_w1p[64 * 16];
    __shared__ float s_w2[64];

    const int tid = threadIdx.x;
    for (int i = tid; i < 64 * 16; i += 256) s_w1p[i] = g_w1p[i];
    if (tid < 64) s_w2[tid] = w2[tid];
    __syncthreads();

    const int lane = tid & 31;
    const int warp = tid >> 5;
    const int q = lane & 1;             // which x-corner this lane owns
    const int lp = lane >> 1;           // local point within warp (0..15)

    for (int b = blockIdx.x; b < NBATCH; b += NCTA) {
        // this warp handles 16 consecutive points
        const int p0 = b * 128 + warp * 16;
        const int p = p0 + lp;

        // cooperative point load: 48 floats for the warp, 2 coalesced LDG
        const float* __restrict__ pbase = pts + (size_t)p0 * 3;
        const float v0 = pbase[lane];
        const float v1 = (lane < 16) ? pbase[32 + lane] : 0.0f;

        float crd[3];
#pragma unroll
        for (int d = 0; d < 3; ++d) {
            const int k = 3 * lp + d;
            const float a0 = __shfl_sync(0xffffffffu, v0, k & 31);
            const float a1 = __shfl_sync(0xffffffffu, v1, k & 31);
            crd[d] = (k < 32) ? a0 : a1;
        }
        const float px = crd[0], py = crd[1], pz = crd[2];

        __nv_bfloat162 enc2[NLEV];      // packed (e0,e1) per level

#pragma unroll
        for (int l = 0; l < NLEV; ++l) {
            const int resi = level_res(l);
            const bool dense = (l < 5);
            const bool keepL1 = (l < 3);    // only these fit in L1
            const float res = (float)resi;

            const float x = px * res, y = py * res, z = pz * res;
            const float fx0 = floorf(x), fy0 = floorf(y), fz0 = floorf(z);
            const float fx = x - fx0, fy = y - fy0, fz = z - fz0;
            const unsigned cx = (unsigned)fx0;
            const unsigned cy = (unsigned)fy0;
            const unsigned cz = (unsigned)fz0;

            const float2* __restrict__ tab = table + (size_t)l * TSIZE;

            const unsigned ux = cx + (unsigned)q;    // this lane's x corner
            const float wxq = q ? fx : (1.0f - fx);
            const float wy[2] = {1.0f - fy, fy};
            const float wz[2] = {1.0f - fz, fz};

            unsigned iy[2], iz[2];
            if (dense) {
                const unsigned r1 = (unsigned)(resi + 1);
                iy[0] = r1 * cy;       iy[1] = r1 * (cy + 1u);
                iz[0] = r1 * r1 * cz;  iz[1] = r1 * r1 * (cz + 1u);
            } else {
                iy[0] = cy * 2654435761u;        iy[1] = (cy + 1u) * 2654435761u;
                iz[0] = cz * 805459861u;         iz[1] = (cz + 1u) * 805459861u;
            }

            // compute all 4 addresses, issue all 4 loads, THEN accumulate
            unsigned idx[4];
#pragma unroll
            for (int c = 0; c < 4; ++c) {
                const int oy = (c >> 1) & 1, oz = c & 1;
                idx[c] = dense ? ((ux + iy[oy] + iz[oz]) & TMASK)
                               : ((ux ^ iy[oy] ^ iz[oz]) & TMASK);
            }
            float2 f[4];
#pragma unroll
            for (int c = 0; c < 4; ++c)
                f[c] = keepL1 ? __ldg(tab + idx[c]) : __ldcg(tab + idx[c]);

            float e0 = 0.0f, e1 = 0.0f;
#pragma unroll
            for (int c = 0; c < 4; ++c) {
                const int oy = (c >> 1) & 1, oz = c & 1;
                const float w = wxq * wy[oy] * wz[oz];
                e0 = fmaf(w, f[c].x, e0);
                e1 = fmaf(w, f[c].y, e1);
            }
            // combine the two x-corner halves across the lane pair
            e0 += __shfl_xor_sync(0xffffffffu, e0, 1);
            e1 += __shfl_xor_sync(0xffffffffu, e1, 1);
            enc2[l] = __floats2bfloat162_rn(e0, e1);
        }

        // MLP in bf16x2: lane q handles rows {2*jj + q} (conflict-free LDS)
        float acc = 0.0f;
#pragma unroll 4
        for (int jj = 0; jj < 32; ++jj) {
            const int row = 2 * jj + q;
            const uint4* __restrict__ wr = (const uint4*)(s_w1p + row * 16);
            __nv_bfloat162 h2 = __floats2bfloat162_rn(0.0f, 0.0f);
#pragma unroll
            for (int r = 0; r < 4; ++r) {
                const uint4 v = wr[r];
                h2 = __hfma2(enc2[4 * r + 0], *(const __nv_bfloat162*)&v.x, h2);
                h2 = __hfma2(enc2[4 * r + 1], *(const __nv_bfloat162*)&v.y, h2);
                h2 = __hfma2(enc2[4 * r + 2], *(const __nv_bfloat162*)&v.z, h2);
                h2 = __hfma2(enc2[4 * r + 3], *(const __nv_bfloat162*)&v.w, h2);
            }
            const float h = __low2float(h2) + __high2float(h2);
            acc = fmaf(s_w2[row], fmaxf(h, 0.0f), acc);
        }
        acc += __shfl_xor_sync(0xffffffffu, acc, 1);
        if (q == 0) out[p] = 1.0f / (1.0f + __expf(-acc));
    }
}

extern "C" void kernel_launch(void* const* d_in, const int* in_sizes, int n_in,
                              void* d_out, int out_size)
{
    const float*  pts   = (const float*)d_in[0];   // [NPTS, 3]
    const float2* table = (const float2*)d_in[1];  // [L, T, 2]
    const float*  w1    = (const float*)d_in[2];   // [64, 32]
    const float*  w2    = (const float*)d_in[3];   // [64]
    float* out = (float*)d_out;

    prep_weights_kernel<<<1, 256>>>(w1);
    ngp_fused_r5_kernel<<<NCTA, 256>>>(pts, table, w2, out);
}

// round 6
// speedup vs baseline: 1.1057x; 1.1057x over previous
#include <cuda_runtime.h>
#include <cuda_bf16.h>
#include <math.h>

// instant-NGP HashGrid + 2-layer MLP, fused. 2 lanes/point (x-corner pairing),
// bf16x2 MLP (HFMA2). R6 = R4 structure (proven 82.4us) + software pipelining
// across levels: next level's 4 gathers are issued before the current level's
// results are consumed (MLP 4 -> 8), regs relaxed to (256,5). Dense levels
// skip the hash mask (provably a no-op).

#define NPTS (64 * 64 * 64)
#define NLEV 16
#define TSIZE (1u << 19)
#define TMASK (TSIZE - 1u)

__device__ __nv_bfloat162 g_w1p[64 * 16];   // [j][l] packed pairs of w1[j, 2l:2l+2]

__global__ void prep_weights_kernel(const float* __restrict__ w1) {
    for (int k = threadIdx.x; k < 64 * 16; k += 256) {
        const int j = k >> 4, l = k & 15;
        g_w1p[k] = __floats2bfloat162_rn(w1[j * 32 + 2 * l], w1[j * 32 + 2 * l + 1]);
    }
}

__device__ __forceinline__ int level_res(int l) {
    const int R[NLEV] = {16, 23, 33, 48, 70, 101, 147, 212,
                         307, 445, 645, 933, 1351, 1955, 2830, 4096};
    return R[l];
}

// Compute the 4 gather indices + 4 trilinear weights for level l (this lane's
// x-corner fixed by q).
__device__ __forceinline__ void level_setup(int l, float px, float py, float pz,
                                            unsigned q, unsigned idx[4], float w[4])
{
    const int resi = level_res(l);
    const bool dense = (l < 5);
    const float res = (float)resi;

    const float x = px * res, y = py * res, z = pz * res;
    const float fx0 = floorf(x), fy0 = floorf(y), fz0 = floorf(z);
    const float fx = x - fx0, fy = y - fy0, fz = z - fz0;
    const unsigned cx = (unsigned)fx0;
    const unsigned cy = (unsigned)fy0;
    const unsigned cz = (unsigned)fz0;

    const unsigned ux = cx + q;
    const float wxq = q ? fx : (1.0f - fx);
    const float wy[2] = {1.0f - fy, fy};
    const float wz[2] = {1.0f - fz, fz};

    unsigned iy[2], iz[2];
    if (dense) {
        const unsigned r1 = (unsigned)(resi + 1);
        iy[0] = r1 * cy;       iy[1] = r1 * (cy + 1u);
        iz[0] = r1 * r1 * cz;  iz[1] = r1 * r1 * (cz + 1u);
    } else {
        iy[0] = cy * 2654435761u;        iy[1] = (cy + 1u) * 2654435761u;
        iz[0] = cz * 805459861u;         iz[1] = (cz + 1u) * 805459861u;
    }

#pragma unroll
    for (int c = 0; c < 4; ++c) {
        const int oy = (c >> 1) & 1, oz = c & 1;
        // dense indices are < (res+1)^3 <= T, so the mask is a no-op there
        idx[c] = dense ? (ux + iy[oy] + iz[oz])
                       : ((ux ^ iy[oy] ^ iz[oz]) & TMASK);
        w[c] = wxq * wy[oy] * wz[oz];
    }
}

__device__ __forceinline__ void level_load(int l, const float2* __restrict__ table,
                                           const unsigned idx[4], float2 f[4])
{
    const float2* __restrict__ tab = table + (size_t)l * TSIZE;
    const bool keepL1 = (l < 3);   // only levels 0-2 fit in L1
#pragma unroll
    for (int c = 0; c < 4; ++c)
        f[c] = keepL1 ? __ldg(tab + idx[c]) : __ldcg(tab + idx[c]);
}

__global__ void __launch_bounds__(256, 5)
ngp_fused_r6_kernel(const float* __restrict__ pts,
                    const float2* __restrict__ table,   // [L*T] float2
                    const float* __restrict__ w2,       // [64]
                    float* __restrict__ out)            // [NPTS]
{
    __shared__ __nv_bfloat162 s_w1p[64 * 16];
    __shared__ float s_w2[64];

    const int tid = threadIdx.x;
    for (int i = tid; i < 64 * 16; i += 256) s_w1p[i] = g_w1p[i];
    if (tid < 64) s_w2[tid] = w2[tid];
    __syncthreads();

    const int t = blockIdx.x * 256 + tid;
    const int p = t >> 1;              // point id
    const unsigned q = (unsigned)(t & 1);

    const float px = pts[3 * p + 0];
    const float py = pts[3 * p + 1];
    const float pz = pts[3 * p + 2];

    __nv_bfloat162 enc2[NLEV];

    // --- software-pipelined gather: loads for level l+1 in flight while
    // level l is reduced ---
    unsigned idx_n[4];
    float    w_c[4], w_n[4];
    float2   f_c[4], f_n[4];

    level_setup(0, px, py, pz, q, idx_n, w_c);
    level_load(0, table, idx_n, f_c);

#pragma unroll
    for (int l = 0; l < NLEV; ++l) {
        if (l + 1 < NLEV) {
            level_setup(l + 1, px, py, pz, q, idx_n, w_n);
            level_load(l + 1, table, idx_n, f_n);
        }

        float e0 = 0.0f, e1 = 0.0f;
#pragma unroll
        for (int c = 0; c < 4; ++c) {
            e0 = fmaf(w_c[c], f_c[c].x, e0);
            e1 = fmaf(w_c[c], f_c[c].y, e1);
        }
        e0 += __shfl_xor_sync(0xffffffffu, e0, 1);
        e1 += __shfl_xor_sync(0xffffffffu, e1, 1);
        enc2[l] = __floats2bfloat162_rn(e0, e1);

#pragma unroll
        for (int c = 0; c < 4; ++c) { f_c[c] = f_n[c]; w_c[c] = w_n[c]; }
    }

    // MLP in bf16x2: lane q handles rows {2*jj + q} (conflict-free LDS)
    float acc = 0.0f;
#pragma unroll 4
    for (int jj = 0; jj < 32; ++jj) {
        const int row = 2 * jj + (int)q;
        const uint4* __restrict__ wr = (const uint4*)(s_w1p + row * 16);
        __nv_bfloat162 h2 = __floats2bfloat162_rn(0.0f, 0.0f);
#pragma unroll
        for (int r = 0; r < 4; ++r) {
            const uint4 v = wr[r];
            h2 = __hfma2(enc2[4 * r + 0], *(const __nv_bfloat162*)&v.x, h2);
            h2 = __hfma2(enc2[4 * r + 1], *(const __nv_bfloat162*)&v.y, h2);
            h2 = __hfma2(enc2[4 * r + 2], *(const __nv_bfloat162*)&v.z, h2);
            h2 = __hfma2(enc2[4 * r + 3], *(const __nv_bfloat162*)&v.w, h2);
        }
        const float h = __low2float(h2) + __high2float(h2);
        acc = fmaf(s_w2[row], fmaxf(h, 0.0f), acc);
    }
    acc += __shfl_xor_sync(0xffffffffu, acc, 1);
    if (q == 0) out[p] = 1.0f / (1.0f + __expf(-acc));
}

extern "C" void kernel_launch(void* const* d_in, const int* in_sizes, int n_in,
                              void* d_out, int out_size)
{
    const float*  pts   = (const float*)d_in[0];   // [NPTS, 3]
    const float2* table = (const float2*)d_in[1];  // [L, T, 2]
    const float*  w1    = (const float*)d_in[2];   // [64, 32]
    const float*  w2    = (const float*)d_in[3];   // [64]
    float* out = (float*)d_out;

    prep_weights_kernel<<<1, 256>>>(w1);
    ngp_fused_r6_kernel<<<(NPTS * 2) / 256, 256>>>(pts, table, w2, out);
}

// round 9
// speedup vs baseline: 1.1666x; 1.0551x over previous
#include <cuda_runtime.h>
#include <cuda_bf16.h>
#include <math.h>
#include <stdint.h>

// instant-NGP HashGrid + MLP. Gather: R6 (2 lanes/point, software-pipelined).
// MLP: warp-level tensor cores (mma.sync.m16n8k16 bf16, fp32 accum), sm_100
// baseline PTX (no tcgen05 -- unavailable in this build's PTX target).
// Per warp: D[16 pts, 64 hidden] = A[16,32] x B[32,64]; 16 MMAs.

#define NPTS (64 * 64 * 64)
#define NLEV 16
#define TSIZE (1u << 19)
#define TMASK (TSIZE - 1u)

#define ROWB 80   // A-tile row stride in bytes (conflict-free STS, 16B-aligned)

// Precomputed per-lane B fragments: [ (nt*2+s) ][ lane ] -> {b0, b1}
__device__ uint2 g_bfrag[16 * 32];

__global__ void prep_bfrag_kernel(const float* __restrict__ w1) {
    const int k = threadIdx.x;              // 0..511
    const int lane = k & 31;
    const int ts = k >> 5;                  // nt*2+s
    const int nt = ts >> 1, s = ts & 1;
    const int g = lane >> 2, t = lane & 3;
    const int row = 8 * nt + g;             // hidden unit j
    const int k0 = 16 * s + 2 * t;
    uint2 v;
    __nv_bfloat162 b0 = __floats2bfloat162_rn(w1[row * 32 + k0],     w1[row * 32 + k0 + 1]);
    __nv_bfloat162 b1 = __floats2bfloat162_rn(w1[row * 32 + k0 + 8], w1[row * 32 + k0 + 9]);
    v.x = *(uint32_t*)&b0;
    v.y = *(uint32_t*)&b1;
    g_bfrag[k] = v;
}

__device__ __forceinline__ int level_res(int l) {
    const int R[NLEV] = {16, 23, 33, 48, 70, 101, 147, 212,
                         307, 445, 645, 933, 1351, 1955, 2830, 4096};
    return R[l];
}

__device__ __forceinline__ void level_setup(int l, float px, float py, float pz,
                                            unsigned q, unsigned idx[4], float w[4])
{
    const int resi = level_res(l);
    const bool dense = (l < 5);
    const float res = (float)resi;

    const float x = px * res, y = py * res, z = pz * res;
    const float fx0 = floorf(x), fy0 = floorf(y), fz0 = floorf(z);
    const float fx = x - fx0, fy = y - fy0, fz = z - fz0;
    const unsigned cx = (unsigned)fx0;
    const unsigned cy = (unsigned)fy0;
    const unsigned cz = (unsigned)fz0;

    const unsigned ux = cx + q;
    const float wxq = q ? fx : (1.0f - fx);
    const float wy[2] = {1.0f - fy, fy};
    const float wz[2] = {1.0f - fz, fz};

    unsigned iy[2], iz[2];
    if (dense) {
        const unsigned r1 = (unsigned)(resi + 1);
        iy[0] = r1 * cy;       iy[1] = r1 * (cy + 1u);
        iz[0] = r1 * r1 * cz;  iz[1] = r1 * r1 * (cz + 1u);
    } else {
        iy[0] = cy * 2654435761u;        iy[1] = (cy + 1u) * 2654435761u;
        iz[0] = cz * 805459861u;         iz[1] = (cz + 1u) * 805459861u;
    }

#pragma unroll
    for (int c = 0; c < 4; ++c) {
        const int oy = (c >> 1) & 1, oz = c & 1;
        idx[c] = dense ? (ux + iy[oy] + iz[oz])            // < (res+1)^3 <= T
                       : ((ux ^ iy[oy] ^ iz[oz]) & TMASK);
        w[c] = wxq * wy[oy] * wz[oz];
    }
}

__device__ __forceinline__ void level_load(int l, const float2* __restrict__ table,
                                           const unsigned idx[4], float2 f[4])
{
    const float2* __restrict__ tab = table + (size_t)l * TSIZE;
    const bool keepL1 = (l < 3);
#pragma unroll
    for (int c = 0; c < 4; ++c)
        f[c] = keepL1 ? __ldg(tab + idx[c]) : __ldcg(tab + idx[c]);
}

__global__ void __launch_bounds__(256, 5)
ngp_fused_mma_kernel(const float* __restrict__ pts,
                     const float2* __restrict__ table,   // [L*T] float2
                     const float* __restrict__ w2,       // [64]
                     float* __restrict__ out)            // [NPTS]
{
    __shared__ char s_enc[8 * 16 * ROWB];   // 8 warps x 16 rows x 80B
    __shared__ uint2 s_bfrag[16 * 32];      // 4KB B fragment table
    __shared__ float s_w2[64];

    const int tid = threadIdx.x;
    const int wid = tid >> 5;
    const int lane = tid & 31;

    for (int i = tid; i < 16 * 32; i += 256) s_bfrag[i] = g_bfrag[i];
    if (tid < 64) s_w2[tid] = w2[tid];
    __syncthreads();

    // ---------- gather (R6 pipelined structure, unchanged) ----------
    const int t = blockIdx.x * 256 + tid;
    const int p = t >> 1;                  // global point id
    const unsigned q = (unsigned)(t & 1);

    const float px = pts[3 * p + 0];
    const float py = pts[3 * p + 1];
    const float pz = pts[3 * p + 2];

    __nv_bfloat162 enc2[NLEV];

    unsigned idx_n[4];
    float    w_c[4], w_n[4];
    float2   f_c[4], f_n[4];

    level_setup(0, px, py, pz, q, idx_n, w_c);
    level_load(0, table, idx_n, f_c);

#pragma unroll
    for (int l = 0; l < NLEV; ++l) {
        if (l + 1 < NLEV) {
            level_setup(l + 1, px, py, pz, q, idx_n, w_n);
            level_load(l + 1, table, idx_n, f_n);
        }
        float e0 = 0.0f, e1 = 0.0f;
#pragma unroll
        for (int c = 0; c < 4; ++c) {
            e0 = fmaf(w_c[c], f_c[c].x, e0);
            e1 = fmaf(w_c[c], f_c[c].y, e1);
        }
        e0 += __shfl_xor_sync(0xffffffffu, e0, 1);
        e1 += __shfl_xor_sync(0xffffffffu, e1, 1);
        enc2[l] = __floats2bfloat162_rn(e0, e1);
#pragma unroll
        for (int c = 0; c < 4; ++c) { f_c[c] = f_n[c]; w_c[c] = w_n[c]; }
    }

    // ---------- stage A tile: 16 rows (points) x 32 bf16, row stride 80B ----------
    char* aw = s_enc + wid * (16 * ROWB);
    if (q == 0u) {
        const int row = (tid >> 1) & 15;    // local point within warp
        char* rb = aw + row * ROWB;
#pragma unroll
        for (int r = 0; r < 4; ++r) {
            uint4 v;
            v.x = *(const uint32_t*)&enc2[4 * r + 0];
            v.y = *(const uint32_t*)&enc2[4 * r + 1];
            v.z = *(const uint32_t*)&enc2[4 * r + 2];
            v.w = *(const uint32_t*)&enc2[4 * r + 3];
            *(uint4*)(rb + 16 * r) = v;
        }
    }
    __syncwarp();

    // ---------- load A fragments via ldmatrix (2 k-steps) ----------
    // ldmatrix.x4 address pattern: lanes 0-7 rows0-7, 8-15 rows8-15 (first
    // 16B col-chunk); 16-23 rows0-7, 24-31 rows8-15 (second 16B chunk).
    const int lrow = (lane & 7) + ((lane >> 3) & 1) * 8;
    const int lcol = (lane >> 4) * 16;
    uint32_t a0[4], a1[4];
    {
        uint32_t addr0 = (uint32_t)__cvta_generic_to_shared(aw + lrow * ROWB + lcol);
        asm volatile("ldmatrix.sync.aligned.m8n8.x4.shared.b16 {%0,%1,%2,%3}, [%4];"
                     : "=r"(a0[0]), "=r"(a0[1]), "=r"(a0[2]), "=r"(a0[3]) : "r"(addr0));
        asm volatile("ldmatrix.sync.aligned.m8n8.x4.shared.b16 {%0,%1,%2,%3}, [%4];"
                     : "=r"(a1[0]), "=r"(a1[1]), "=r"(a1[2]), "=r"(a1[3]) : "r"(addr0 + 32));
    }

    // ---------- 16x mma.sync + fused relu*w2 epilogue ----------
    const int g = lane >> 2, tt = lane & 3;
    float acc0 = 0.0f, acc1 = 0.0f;      // rows g and g+8 of this warp's tile
#pragma unroll
    for (int nt = 0; nt < 8; ++nt) {
        float d0 = 0.0f, d1 = 0.0f, d2 = 0.0f, d3 = 0.0f;
        const uint2 b0 = s_bfrag[(nt * 2 + 0) * 32 + lane];
        const uint2 b1 = s_bfrag[(nt * 2 + 1) * 32 + lane];
        asm volatile(
            "mma.sync.aligned.m16n8k16.row.col.f32.bf16.bf16.f32 "
            "{%0,%1,%2,%3}, {%4,%5,%6,%7}, {%8,%9}, {%0,%1,%2,%3};"
            : "+f"(d0), "+f"(d1), "+f"(d2), "+f"(d3)
            : "r"(a0[0]), "r"(a0[1]), "r"(a0[2]), "r"(a0[3]), "r"(b0.x), "r"(b0.y));
        asm volatile(
            "mma.sync.aligned.m16n8k16.row.col.f32.bf16.bf16.f32 "
            "{%0,%1,%2,%3}, {%4,%5,%6,%7}, {%8,%9}, {%0,%1,%2,%3};"
            : "+f"(d0), "+f"(d1), "+f"(d2), "+f"(d3)
            : "r"(a1[0]), "r"(a1[1]), "r"(a1[2]), "r"(a1[3]), "r"(b1.x), "r"(b1.y));

        const float w2a = s_w2[8 * nt + 2 * tt];
        const float w2b = s_w2[8 * nt + 2 * tt + 1];
        acc0 = fmaf(w2a, fmaxf(d0, 0.0f), acc0);
        acc0 = fmaf(w2b, fmaxf(d1, 0.0f), acc0);
        acc1 = fmaf(w2a, fmaxf(d2, 0.0f), acc1);
        acc1 = fmaf(w2b, fmaxf(d3, 0.0f), acc1);
    }
    // reduce over the 4 lanes (tt) of each row group
    acc0 += __shfl_xor_sync(0xffffffffu, acc0, 1);
    acc0 += __shfl_xor_sync(0xffffffffu, acc0, 2);
    acc1 += __shfl_xor_sync(0xffffffffu, acc1, 1);
    acc1 += __shfl_xor_sync(0xffffffffu, acc1, 2);

    if (tt == 0) {
        const int pbase = blockIdx.x * 128 + wid * 16;
        out[pbase + g]     = 1.0f / (1.0f + __expf(-acc0));
        out[pbase + g + 8] = 1.0f / (1.0f + __expf(-acc1));
    }
}

extern "C" void kernel_launch(void* const* d_in, const int* in_sizes, int n_in,
                              void* d_out, int out_size)
{
    const float*  pts   = (const float*)d_in[0];   // [NPTS, 3]
    const float2* table = (const float2*)d_in[1];  // [L, T, 2]
    const float*  w1    = (const float*)d_in[2];   // [64, 32]
    const float*  w2    = (const float*)d_in[3];   // [64]
    float* out = (float*)d_out;

    prep_bfrag_kernel<<<1, 512>>>(w1);
    ngp_fused_mma_kernel<<<(NPTS * 2) / 256, 256>>>(pts, table, w2, out);
}